// round 16
// baseline (speedup 1.0000x reference)
#include <cuda_runtime.h>
#include <math.h>

#define T_ 256
#define N_ 64
#define C_ 4096
#define L_ 32
#define S_ 65           // 2*L+1
#define BLANK_ 0
#define LOG2E 1.4426950408889634f
#define LN2   0.6931471805599453f

#define TP_ (T_ + 16)
#define DEPTH 16
#define NCONS 64                 // consumer blocks (bids 0..63)
#define NPROD (T_ * N_)          // producer blocks
#define NBLK  (NCONS + NPROD)

// Scratch, layout [n][t][s]: LINEAR probabilities of the 65 extended labels.
__device__ __align__(16) float g_p_ext[N_ * TP_ * S_ + 128];
__device__ float g_per_n[N_];
__device__ int   g_cnt[T_];      // rows completed per timestep (0..64)
__device__ unsigned g_blkdone;   // 0..NBLK; reset by last block each run

__device__ __forceinline__ float ex2(float x) {
    float y; asm("ex2.approx.ftz.f32 %0, %1;" : "=f"(y) : "f"(x)); return y;
}
__device__ __forceinline__ float lg2(float x) {
    float y; asm("lg2.approx.ftz.f32 %0, %1;" : "=f"(y) : "f"(x)); return y;
}
__device__ __forceinline__ float ldcg_f(const float* p) {
    float v; asm volatile("ld.global.cg.f32 %0, [%1];" : "=f"(v) : "l"(p)); return v;
}
__device__ __forceinline__ int ldcg_i(const int* p) {
    int v; asm volatile("ld.global.cg.s32 %0, [%1];" : "=r"(v) : "l"(p)); return v;
}
__device__ __forceinline__ unsigned redux_max_u32(unsigned v) {
    unsigned r;
    asm volatile("redux.sync.max.u32 %0, %1, 0xffffffff;" : "=r"(r) : "r"(v));
    return r;
}

__device__ __forceinline__ bool skip_at(const int* __restrict__ targets, int n, int s) {
    if (s < S_ && (s & 1) && s >= 2) {
        int lab  = targets[n * L_ + (s >> 1)];
        int lab2 = targets[n * L_ + (s >> 1) - 1];
        return (lab != BLANK_) && (lab != lab2);
    }
    return false;
}

// ascending watermark: rows [0, wm) confirmed complete (cnt == N_)
__device__ __forceinline__ void ensure_asc(int& wm, int target, int lane) {
    if (wm > target) return;
    const unsigned FULL = 0xffffffffu;
    while (wm <= target) {
        int idx = wm + lane;
        int c = N_;
        if (idx < T_) c = ldcg_i(g_cnt + idx);
        unsigned mask = __ballot_sync(FULL, c >= N_);
        unsigned inv = ~mask;
        wm += inv ? (__ffs(inv) - 1) : 32;
    }
    __threadfence();   // acquire
}

// descending watermark: rows (255-wmb, 255] confirmed complete
__device__ __forceinline__ void ensure_desc(int& wmb, int target, int lane) {
    int need = T_ - target;            // wmb >= need  <=>  row `target` ready
    if (wmb >= need) return;
    const unsigned FULL = 0xffffffffu;
    while (wmb < need) {
        int idx = (T_ - 1) - (wmb + lane);
        int c = N_;
        if (idx >= 0) c = ldcg_i(g_cnt + idx);
        unsigned mask = __ballot_sync(FULL, c >= N_);
        unsigned inv = ~mask;
        wmb += inv ? (__ffs(inv) - 1) : 32;
    }
    __threadfence();   // acquire
}

// Fused kernel. Bids 0..63: consumers (wave-1 resident). Bids 64..: producers.
__global__ void __launch_bounds__(256) ctc_fused_kernel(
    const float* __restrict__ preds,
    const int*   __restrict__ targets,
    const int*   __restrict__ pred_lengths,
    const int*   __restrict__ target_lengths,
    float*       __restrict__ out)
{
    const unsigned FULL = 0xffffffffu;
    const int tid = threadIdx.x;

    if (blockIdx.x >= NCONS) {
        // ───────────────────── producer (round-13 kernel 1 + signal) ─────
        const int j  = blockIdx.x - NCONS;
        const int st = j & 1;              // 0 = fwd stream, 1 = bwd stream
        const int k  = j >> 1;             // 0..8191
        const int t  = st ? (T_ - 1 - k / N_) : (k / N_);
        const int n  = k % N_;
        const float* __restrict__ p = preds + ((size_t)t * N_ + n) * C_;

        float v[16];
        const float4* __restrict__ p4 = (const float4*)p;
        #pragma unroll
        for (int q = 0; q < 4; q++) {
            float4 f = __ldcs(p4 + tid + q * 256);     // streaming read
            v[q*4+0] = f.x; v[q*4+1] = f.y; v[q*4+2] = f.z; v[q*4+3] = f.w;
        }

        float m = v[0];
        #pragma unroll
        for (int i = 1; i < 16; i++) m = fmaxf(m, v[i]);
        #pragma unroll
        for (int o = 16; o > 0; o >>= 1) m = fmaxf(m, __shfl_xor_sync(FULL, m, o));
        __shared__ float sm[8];
        if ((tid & 31) == 0) sm[tid >> 5] = m;
        __syncthreads();
        float bm = sm[0];
        #pragma unroll
        for (int i = 1; i < 8; i++) bm = fmaxf(bm, sm[i]);
        __syncthreads();

        const float bmL = bm * LOG2E;
        float s = 0.0f;
        #pragma unroll
        for (int i = 0; i < 16; i++) s += ex2(fmaf(v[i], LOG2E, -bmL));
        #pragma unroll
        for (int o = 16; o > 0; o >>= 1) s += __shfl_xor_sync(FULL, s, o);
        if ((tid & 31) == 0) sm[tid >> 5] = s;
        __syncthreads();
        float bs = sm[0];
        #pragma unroll
        for (int i = 1; i < 8; i++) bs += sm[i];

        const float lse = bm + lg2(bs) * LN2;

        if (tid < S_) {
            int label = (tid & 1) ? targets[n * L_ + (tid >> 1)] : BLANK_;
            g_p_ext[(n * TP_ + t) * S_ + tid] = ex2((p[label] - lse) * LOG2E);
        }
        __syncthreads();
        if (tid == 0) {
            __threadfence();                 // publish row before signaling
            atomicAdd(&g_cnt[t], 1);
        }
    } else {
        // ───────────────────── consumer (round-15 logic, verbatim) ───────
        const int warp = tid >> 5;
        const int lane = tid & 31;
        const int n    = blockIdx.x;

        const int tl = target_lengths[n];
        const int pl = pred_lengths[n];
        const int Sv = 2 * tl + 1;
        const int s0 = 3 * lane;

        __shared__ float sA[96];
        __shared__ float sG[96];
        __shared__ int   sE[2];

        if (warp < 2) {
            const bool fwd = (warp == 0);
            bool valid[3];
            #pragma unroll
            for (int jj = 0; jj < 3; jj++)
                valid[jj] = ((s0 + jj) < S_) && ((s0 + jj) < Sv);

            const float* __restrict__ pn = g_p_ext + n * (TP_ * S_);
            float a[3];
            int E = 0;
            float lp[DEPTH][3];

            if (fwd) {
                bool skip[3];
                #pragma unroll
                for (int jj = 0; jj < 3; jj++) skip[jj] = skip_at(targets, n, s0 + jj);

                int wm = 0;
                ensure_asc(wm, 16, lane);        // rows 0..16 ready

                {
                    float p0 = ldcg_f(pn + 0), p1 = ldcg_f(pn + 1);
                    #pragma unroll
                    for (int jj = 0; jj < 3; jj++) {
                        int s = s0 + jj;
                        float a0 = 0.0f;
                        if (s == 0) a0 = p0;
                        if (s == 1 && tl > 0) a0 = p1;
                        a[jj] = valid[jj] ? a0 : 0.0f;
                    }
                }

                #pragma unroll
                for (int jj = 0; jj < DEPTH; jj++) {
                    const float* r = pn + (1 + jj) * S_ + s0;
                    lp[jj][0] = ldcg_f(r); lp[jj][1] = ldcg_f(r + 1); lp[jj][2] = ldcg_f(r + 2);
                }

                #pragma unroll 16
                for (int t = 1; t <= 128; t++) {
                    const int u = (t - 1) & (DEPTH - 1);
                    float l0 = lp[u][0], l1 = lp[u][1], l2 = lp[u][2];
                    {
                        int rowf = t + DEPTH; if (rowf > 127) rowf = 127;
                        ensure_asc(wm, rowf, lane);
                        const float* r = pn + rowf * S_ + s0;
                        lp[u][0] = ldcg_f(r); lp[u][1] = ldcg_f(r + 1); lp[u][2] = ldcg_f(r + 2);
                    }

                    float nb1 = __shfl_up_sync(FULL, a[1], 1);   // state s0-2
                    float nb2 = __shfl_up_sync(FULL, a[2], 1);   // state s0-1
                    if (lane == 0) { nb1 = 0.0f; nb2 = 0.0f; }

                    float c0 = a[0] + nb2  + (skip[0] ? nb1  : 0.0f);
                    float c1 = a[1] + a[0] + (skip[1] ? nb2  : 0.0f);
                    float c2 = a[2] + a[1] + (skip[2] ? a[0] : 0.0f);

                    if (t < 128 && t < pl) {
                        a[0] = valid[0] ? (c0 * l0) : 0.0f;
                        a[1] = valid[1] ? (c1 * l1) : 0.0f;
                        a[2] = valid[2] ? (c2 * l2) : 0.0f;
                    }

                    if ((t & 3) == 0) {
                        float mx = fmaxf(fmaxf(a[0], a[1]), a[2]);
                        unsigned mb = redux_max_u32(__float_as_uint(mx));
                        if (mb >= 0x00800000u) {
                            int e = (int)(mb >> 23) - 127;
                            float sc = __uint_as_float((unsigned)(127 - e) << 23);
                            a[0] *= sc; a[1] *= sc; a[2] *= sc;
                            E += e;
                        }
                    }
                }
                sA[s0] = a[0]; sA[s0 + 1] = a[1]; sA[s0 + 2] = a[2];
                if (lane == 0) sE[0] = E;
            } else {
                bool sk2 = skip_at(targets, n, s0 + 2);
                bool sk3 = skip_at(targets, n, s0 + 3);
                bool sk4 = skip_at(targets, n, s0 + 4);

                int wmb = 0;
                ensure_desc(wmb, 240, lane);     // rows 255..240 ready

                const int end = 2 * tl;
                #pragma unroll
                for (int jj = 0; jj < 3; jj++) {
                    int s = s0 + jj;
                    float g0 = 0.0f;
                    if (s == end) g0 = 1.0f;
                    if (tl > 0 && s == end - 1) g0 = 1.0f;
                    a[jj] = valid[jj] ? g0 : 0.0f;
                }

                #pragma unroll
                for (int jj = 0; jj < DEPTH; jj++) {
                    const float* r = pn + (255 - jj) * S_ + s0;
                    lp[jj][0] = ldcg_f(r); lp[jj][1] = ldcg_f(r + 1); lp[jj][2] = ldcg_f(r + 2);
                }

                #pragma unroll 16
                for (int td = 0; td < 128; td++) {
                    const int u = td & (DEPTH - 1);
                    const int t = 255 - td;
                    float l0 = lp[u][0], l1 = lp[u][1], l2 = lp[u][2];
                    {
                        int rowb = t - DEPTH; if (rowb < 128) rowb = 128;
                        ensure_desc(wmb, rowb, lane);
                        const float* r = pn + rowb * S_ + s0;
                        lp[u][0] = ldcg_f(r); lp[u][1] = ldcg_f(r + 1); lp[u][2] = ldcg_f(r + 2);
                    }

                    float h0 = a[0] * l0;
                    float h1 = a[1] * l1;
                    float h2 = a[2] * l2;
                    float hd0 = __shfl_down_sync(FULL, h0, 1);   // state s0+3
                    float hd1 = __shfl_down_sync(FULL, h1, 1);   // state s0+4
                    if (lane == 31) { hd0 = 0.0f; hd1 = 0.0f; }

                    if (t < pl) {
                        a[0] = valid[0] ? (h0 + h1  + (sk2 ? h2  : 0.0f)) : 0.0f;
                        a[1] = valid[1] ? (h1 + h2  + (sk3 ? hd0 : 0.0f)) : 0.0f;
                        a[2] = valid[2] ? (h2 + hd0 + (sk4 ? hd1 : 0.0f)) : 0.0f;
                    }

                    if ((td & 3) == 3) {
                        float mx = fmaxf(fmaxf(a[0], a[1]), a[2]);
                        unsigned mb = redux_max_u32(__float_as_uint(mx));
                        if (mb >= 0x00800000u) {
                            int e = (int)(mb >> 23) - 127;
                            float sc = __uint_as_float((unsigned)(127 - e) << 23);
                            a[0] *= sc; a[1] *= sc; a[2] *= sc;
                            E += e;
                        }
                    }
                }
                sG[s0] = a[0]; sG[s0 + 1] = a[1]; sG[s0 + 2] = a[2];
                if (lane == 0) sE[1] = E;
            }
        }

        __syncthreads();   // all 8 warps participate

        // combine (warp 0): P = <alpha_127, g_128> * 2^(Ef+Eb)
        if (warp == 0) {
            float dot = sA[s0]     * sG[s0]
                      + sA[s0 + 1] * sG[s0 + 1]
                      + sA[s0 + 2] * sG[s0 + 2];
            #pragma unroll
            for (int o = 16; o > 0; o >>= 1) dot += __shfl_xor_sync(FULL, dot, o);

            if (lane == 0) {
                float nll = -(logf(dot) + (float)(sE[0] + sE[1]) * LN2);
                if (!isfinite(nll) || nll >= 1e29f) nll = 0.0f;
                int denom = tl > 0 ? tl : 1;
                g_per_n[n] = nll / (float)denom;
            }
        }
        __syncthreads();
    }

    // ── last-block-done finalize + signal reset (non-blocking) ──
    if (tid == 0) {
        __threadfence();
        unsigned old = atomicAdd(&g_blkdone, 1u);
        if (old == (unsigned)(NBLK - 1)) {
            __threadfence();
            float acc = 0.0f;
            #pragma unroll
            for (int i = 0; i < N_; i++) acc += ldcg_f(g_per_n + i);
            out[0] = acc / (float)N_;
            for (int i = 0; i < T_; i++) g_cnt[i] = 0;   // reset for replay
            g_blkdone = 0u;
        }
    }
}

extern "C" void kernel_launch(void* const* d_in, const int* in_sizes, int n_in,
                              void* d_out, int out_size)
{
    const float* preds          = (const float*)d_in[0];
    const int*   targets        = (const int*)d_in[1];
    const int*   pred_lengths   = (const int*)d_in[2];
    const int*   target_lengths = (const int*)d_in[3];
    float* out = (float*)d_out;

    ctc_fused_kernel<<<NBLK, 256>>>(preds, targets, pred_lengths,
                                    target_lengths, out);
}

// round 17
// speedup vs baseline: 1.7551x; 1.7551x over previous
#include <cuda_runtime.h>
#include <math.h>

#define T_ 256
#define N_ 64
#define C_ 4096
#define L_ 32
#define S_ 65           // 2*L+1
#define BLANK_ 0
#define LOG2E 1.4426950408889634f
#define LN2   0.6931471805599453f

#define TP_ (T_ + 16)
#define DEPTH 8                  // smaller pipeline: consumer is producer-paced
#define NCONS 64                 // consumer blocks (bids 0..63, wave-1 resident)
#define NPROD (T_ * N_)          // producer blocks
#define NBLK  (NCONS + NPROD)

// Scratch, layout [n][t][s]: LINEAR probabilities of the 65 extended labels.
__device__ __align__(16) float g_p_ext[N_ * TP_ * S_ + 128];
__device__ float g_per_n[N_];
__device__ int   g_cnt[T_];      // rows completed per timestep (0..64)
__device__ unsigned g_blkdone;   // 0..NBLK; reset by last block each run

__device__ __forceinline__ float ex2(float x) {
    float y; asm("ex2.approx.ftz.f32 %0, %1;" : "=f"(y) : "f"(x)); return y;
}
__device__ __forceinline__ float lg2(float x) {
    float y; asm("lg2.approx.ftz.f32 %0, %1;" : "=f"(y) : "f"(x)); return y;
}
__device__ __forceinline__ float ldcg_f(const float* p) {
    float v; asm volatile("ld.global.cg.f32 %0, [%1];" : "=f"(v) : "l"(p)); return v;
}
__device__ __forceinline__ int ldcg_i(const int* p) {
    int v; asm volatile("ld.global.cg.s32 %0, [%1];" : "=r"(v) : "l"(p)); return v;
}
__device__ __forceinline__ unsigned redux_max_u32(unsigned v) {
    unsigned r;
    asm volatile("redux.sync.max.u32 %0, %1, 0xffffffff;" : "=r"(r) : "r"(v));
    return r;
}

__device__ __forceinline__ bool skip_at(const int* __restrict__ targets, int n, int s) {
    if (s < S_ && (s & 1) && s >= 2) {
        int lab  = targets[n * L_ + (s >> 1)];
        int lab2 = targets[n * L_ + (s >> 1) - 1];
        return (lab != BLANK_) && (lab != lab2);
    }
    return false;
}

// ascending watermark: rows [0, wm) confirmed complete (cnt == N_)
__device__ __forceinline__ void ensure_asc(int& wm, int target, int lane) {
    if (wm > target) return;
    const unsigned FULL = 0xffffffffu;
    while (wm <= target) {
        int idx = wm + lane;
        int c = N_;
        if (idx < T_) c = ldcg_i(g_cnt + idx);
        unsigned mask = __ballot_sync(FULL, c >= N_);
        unsigned inv = ~mask;
        wm += inv ? (__ffs(inv) - 1) : 32;
    }
    __threadfence();   // acquire
}

// descending watermark: rows (255-wmb, 255] confirmed complete
__device__ __forceinline__ void ensure_desc(int& wmb, int target, int lane) {
    int need = T_ - target;            // wmb >= need  <=>  row `target` ready
    if (wmb >= need) return;
    const unsigned FULL = 0xffffffffu;
    while (wmb < need) {
        int idx = (T_ - 1) - (wmb + lane);
        int c = N_;
        if (idx >= 0) c = ldcg_i(g_cnt + idx);
        unsigned mask = __ballot_sync(FULL, c >= N_);
        unsigned inv = ~mask;
        wmb += inv ? (__ffs(inv) - 1) : 32;
    }
    __threadfence();   // acquire
}

// Fused kernel. Bids 0..63: consumers (wave-1 resident). Bids 64..: producers.
// __launch_bounds__(256, 6) caps regs at 42: producer path (needs ~32) keeps
// full occupancy/BW; consumer path spills a little (hidden under producer).
__global__ void __launch_bounds__(256, 6) ctc_fused_kernel(
    const float* __restrict__ preds,
    const int*   __restrict__ targets,
    const int*   __restrict__ pred_lengths,
    const int*   __restrict__ target_lengths,
    float*       __restrict__ out)
{
    const unsigned FULL = 0xffffffffu;
    const int tid = threadIdx.x;

    if (blockIdx.x >= NCONS) {
        // ───────────────────── producer (round-13 kernel 1 + signal) ─────
        const int j  = blockIdx.x - NCONS;
        const int st = j & 1;              // 0 = fwd stream, 1 = bwd stream
        const int k  = j >> 1;             // 0..8191
        const int t  = st ? (T_ - 1 - k / N_) : (k / N_);
        const int n  = k % N_;
        const float* __restrict__ p = preds + ((size_t)t * N_ + n) * C_;

        float v[16];
        const float4* __restrict__ p4 = (const float4*)p;
        #pragma unroll
        for (int q = 0; q < 4; q++) {
            float4 f = __ldcs(p4 + tid + q * 256);     // streaming read
            v[q*4+0] = f.x; v[q*4+1] = f.y; v[q*4+2] = f.z; v[q*4+3] = f.w;
        }

        float m = v[0];
        #pragma unroll
        for (int i = 1; i < 16; i++) m = fmaxf(m, v[i]);
        #pragma unroll
        for (int o = 16; o > 0; o >>= 1) m = fmaxf(m, __shfl_xor_sync(FULL, m, o));
        __shared__ float sm[8];
        if ((tid & 31) == 0) sm[tid >> 5] = m;
        __syncthreads();
        float bm = sm[0];
        #pragma unroll
        for (int i = 1; i < 8; i++) bm = fmaxf(bm, sm[i]);
        __syncthreads();

        const float bmL = bm * LOG2E;
        float s = 0.0f;
        #pragma unroll
        for (int i = 0; i < 16; i++) s += ex2(fmaf(v[i], LOG2E, -bmL));
        #pragma unroll
        for (int o = 16; o > 0; o >>= 1) s += __shfl_xor_sync(FULL, s, o);
        if ((tid & 31) == 0) sm[tid >> 5] = s;
        __syncthreads();
        float bs = sm[0];
        #pragma unroll
        for (int i = 1; i < 8; i++) bs += sm[i];

        const float lse = bm + lg2(bs) * LN2;

        if (tid < S_) {
            int label = (tid & 1) ? targets[n * L_ + (tid >> 1)] : BLANK_;
            g_p_ext[(n * TP_ + t) * S_ + tid] = ex2((p[label] - lse) * LOG2E);
        }
        __syncthreads();
        if (tid == 0) {
            __threadfence();                 // publish row before signaling
            atomicAdd(&g_cnt[t], 1);
        }
    } else {
        // ───────────────────── consumer (round-15/16 logic) ──────────────
        const int warp = tid >> 5;
        const int lane = tid & 31;
        const int n    = blockIdx.x;

        const int tl = target_lengths[n];
        const int pl = pred_lengths[n];
        const int Sv = 2 * tl + 1;
        const int s0 = 3 * lane;

        __shared__ float sA[96];
        __shared__ float sG[96];
        __shared__ int   sE[2];

        if (warp < 2) {
            const bool fwd = (warp == 0);
            bool valid[3];
            #pragma unroll
            for (int jj = 0; jj < 3; jj++)
                valid[jj] = ((s0 + jj) < S_) && ((s0 + jj) < Sv);

            const float* __restrict__ pn = g_p_ext + n * (TP_ * S_);
            float a[3];
            int E = 0;
            float lp[DEPTH][3];

            if (fwd) {
                bool skip[3];
                #pragma unroll
                for (int jj = 0; jj < 3; jj++) skip[jj] = skip_at(targets, n, s0 + jj);

                int wm = 0;
                ensure_asc(wm, DEPTH, lane);     // rows 0..8 ready

                {
                    float p0 = ldcg_f(pn + 0), p1 = ldcg_f(pn + 1);
                    #pragma unroll
                    for (int jj = 0; jj < 3; jj++) {
                        int s = s0 + jj;
                        float a0 = 0.0f;
                        if (s == 0) a0 = p0;
                        if (s == 1 && tl > 0) a0 = p1;
                        a[jj] = valid[jj] ? a0 : 0.0f;
                    }
                }

                #pragma unroll
                for (int jj = 0; jj < DEPTH; jj++) {
                    const float* r = pn + (1 + jj) * S_ + s0;
                    lp[jj][0] = ldcg_f(r); lp[jj][1] = ldcg_f(r + 1); lp[jj][2] = ldcg_f(r + 2);
                }

                #pragma unroll 8
                for (int t = 1; t <= 128; t++) {
                    const int u = (t - 1) & (DEPTH - 1);
                    float l0 = lp[u][0], l1 = lp[u][1], l2 = lp[u][2];
                    {
                        int rowf = t + DEPTH; if (rowf > 127) rowf = 127;
                        ensure_asc(wm, rowf, lane);
                        const float* r = pn + rowf * S_ + s0;
                        lp[u][0] = ldcg_f(r); lp[u][1] = ldcg_f(r + 1); lp[u][2] = ldcg_f(r + 2);
                    }

                    float nb1 = __shfl_up_sync(FULL, a[1], 1);   // state s0-2
                    float nb2 = __shfl_up_sync(FULL, a[2], 1);   // state s0-1
                    if (lane == 0) { nb1 = 0.0f; nb2 = 0.0f; }

                    float c0 = a[0] + nb2  + (skip[0] ? nb1  : 0.0f);
                    float c1 = a[1] + a[0] + (skip[1] ? nb2  : 0.0f);
                    float c2 = a[2] + a[1] + (skip[2] ? a[0] : 0.0f);

                    if (t < 128 && t < pl) {
                        a[0] = valid[0] ? (c0 * l0) : 0.0f;
                        a[1] = valid[1] ? (c1 * l1) : 0.0f;
                        a[2] = valid[2] ? (c2 * l2) : 0.0f;
                    }

                    if ((t & 3) == 0) {
                        float mx = fmaxf(fmaxf(a[0], a[1]), a[2]);
                        unsigned mb = redux_max_u32(__float_as_uint(mx));
                        if (mb >= 0x00800000u) {
                            int e = (int)(mb >> 23) - 127;
                            float sc = __uint_as_float((unsigned)(127 - e) << 23);
                            a[0] *= sc; a[1] *= sc; a[2] *= sc;
                            E += e;
                        }
                    }
                }
                sA[s0] = a[0]; sA[s0 + 1] = a[1]; sA[s0 + 2] = a[2];
                if (lane == 0) sE[0] = E;
            } else {
                bool sk2 = skip_at(targets, n, s0 + 2);
                bool sk3 = skip_at(targets, n, s0 + 3);
                bool sk4 = skip_at(targets, n, s0 + 4);

                int wmb = 0;
                ensure_desc(wmb, T_ - DEPTH, lane);   // rows 255..248 ready

                const int end = 2 * tl;
                #pragma unroll
                for (int jj = 0; jj < 3; jj++) {
                    int s = s0 + jj;
                    float g0 = 0.0f;
                    if (s == end) g0 = 1.0f;
                    if (tl > 0 && s == end - 1) g0 = 1.0f;
                    a[jj] = valid[jj] ? g0 : 0.0f;
                }

                #pragma unroll
                for (int jj = 0; jj < DEPTH; jj++) {
                    const float* r = pn + (255 - jj) * S_ + s0;
                    lp[jj][0] = ldcg_f(r); lp[jj][1] = ldcg_f(r + 1); lp[jj][2] = ldcg_f(r + 2);
                }

                #pragma unroll 8
                for (int td = 0; td < 128; td++) {
                    const int u = td & (DEPTH - 1);
                    const int t = 255 - td;
                    float l0 = lp[u][0], l1 = lp[u][1], l2 = lp[u][2];
                    {
                        int rowb = t - DEPTH; if (rowb < 128) rowb = 128;
                        ensure_desc(wmb, rowb, lane);
                        const float* r = pn + rowb * S_ + s0;
                        lp[u][0] = ldcg_f(r); lp[u][1] = ldcg_f(r + 1); lp[u][2] = ldcg_f(r + 2);
                    }

                    float h0 = a[0] * l0;
                    float h1 = a[1] * l1;
                    float h2 = a[2] * l2;
                    float hd0 = __shfl_down_sync(FULL, h0, 1);   // state s0+3
                    float hd1 = __shfl_down_sync(FULL, h1, 1);   // state s0+4
                    if (lane == 31) { hd0 = 0.0f; hd1 = 0.0f; }

                    if (t < pl) {
                        a[0] = valid[0] ? (h0 + h1  + (sk2 ? h2  : 0.0f)) : 0.0f;
                        a[1] = valid[1] ? (h1 + h2  + (sk3 ? hd0 : 0.0f)) : 0.0f;
                        a[2] = valid[2] ? (h2 + hd0 + (sk4 ? hd1 : 0.0f)) : 0.0f;
                    }

                    if ((td & 3) == 3) {
                        float mx = fmaxf(fmaxf(a[0], a[1]), a[2]);
                        unsigned mb = redux_max_u32(__float_as_uint(mx));
                        if (mb >= 0x00800000u) {
                            int e = (int)(mb >> 23) - 127;
                            float sc = __uint_as_float((unsigned)(127 - e) << 23);
                            a[0] *= sc; a[1] *= sc; a[2] *= sc;
                            E += e;
                        }
                    }
                }
                sG[s0] = a[0]; sG[s0 + 1] = a[1]; sG[s0 + 2] = a[2];
                if (lane == 0) sE[1] = E;
            }
        }

        __syncthreads();   // all 8 warps participate

        // combine (warp 0): P = <alpha_127, g_128> * 2^(Ef+Eb)
        if (warp == 0) {
            float dot = sA[s0]     * sG[s0]
                      + sA[s0 + 1] * sG[s0 + 1]
                      + sA[s0 + 2] * sG[s0 + 2];
            #pragma unroll
            for (int o = 16; o > 0; o >>= 1) dot += __shfl_xor_sync(FULL, dot, o);

            if (lane == 0) {
                float nll = -(logf(dot) + (float)(sE[0] + sE[1]) * LN2);
                if (!isfinite(nll) || nll >= 1e29f) nll = 0.0f;
                int denom = tl > 0 ? tl : 1;
                g_per_n[n] = nll / (float)denom;
            }
        }
        __syncthreads();
    }

    // ── last-block-done finalize + signal reset (non-blocking) ──
    if (tid == 0) {
        __threadfence();
        unsigned old = atomicAdd(&g_blkdone, 1u);
        if (old == (unsigned)(NBLK - 1)) {
            __threadfence();
            float acc = 0.0f;
            #pragma unroll
            for (int i = 0; i < N_; i++) acc += ldcg_f(g_per_n + i);
            out[0] = acc / (float)N_;
            for (int i = 0; i < T_; i++) g_cnt[i] = 0;   // reset for replay
            g_blkdone = 0u;
        }
    }
}

extern "C" void kernel_launch(void* const* d_in, const int* in_sizes, int n_in,
                              void* d_out, int out_size)
{
    const float* preds          = (const float*)d_in[0];
    const int*   targets        = (const int*)d_in[1];
    const int*   pred_lengths   = (const int*)d_in[2];
    const int*   target_lengths = (const int*)d_in[3];
    float* out = (float*)d_out;

    ctc_fused_kernel<<<NBLK, 256>>>(preds, targets, pred_lengths,
                                    target_lengths, out);
}